// round 1
// baseline (speedup 1.0000x reference)
#include <cuda_runtime.h>
#include <math.h>

#define NB 256
#define S  4096
#define FO 8
#define NM 64
#define FM 6
#define EPSF 1e-5f
#define PBLK 16   // reduce blocks per instance

// -------- device scratch (no allocations allowed) --------
__device__ float g_psum[NB];
__device__ float g_psumsq[NB];
__device__ float g_pcnt[NB];
__device__ float g_pmean[NB];
__device__ float g_prstd[NB];
__device__ float g_omean[NB * FO];
__device__ float g_orstd[NB * FO];
__device__ float g_mmean[NB * FM];
__device__ float g_mrstd[NB * FM];

__device__ __forceinline__ float warp_sum(float v) {
#pragma unroll
    for (int o = 16; o > 0; o >>= 1) v += __shfl_down_sync(0xffffffffu, v, o);
    return v;
}

// -------- 1) zero accumulators (runs every graph replay) --------
__global__ void zero_k() {
    int i = blockIdx.x * blockDim.x + threadIdx.x;
    if (i < NB) { g_psum[i] = 0.f; g_psumsq[i] = 0.f; g_pcnt[i] = 0.f; }
}

// -------- 2) proc_time reduction: sum, sumsq, nonzero count per instance --------
__global__ void proc_reduce_k(const float4* __restrict__ pt) {
    const int n4  = (S * NM) / 4;     // 65536 float4 per instance
    const int per = n4 / PBLK;        // 4096 float4 per block
    int b    = blockIdx.x / PBLK;
    int base = b * n4 + (blockIdx.x % PBLK) * per;

    float s = 0.f, ss = 0.f, c = 0.f;
#pragma unroll 4
    for (int i = threadIdx.x; i < per; i += 256) {
        float4 v = pt[base + i];
        s  += (v.x + v.y) + (v.z + v.w);
        ss += (v.x * v.x + v.y * v.y) + (v.z * v.z + v.w * v.w);
        c  += (float)((v.x != 0.f) + (v.y != 0.f) + (v.z != 0.f) + (v.w != 0.f));
    }

    __shared__ float sh[3][8];
    int lane = threadIdx.x & 31, w = threadIdx.x >> 5;
    s = warp_sum(s); ss = warp_sum(ss); c = warp_sum(c);
    if (lane == 0) { sh[0][w] = s; sh[1][w] = ss; sh[2][w] = c; }
    __syncthreads();
    if (threadIdx.x == 0) {
        float ts = 0.f, tss = 0.f, tc = 0.f;
#pragma unroll
        for (int i = 0; i < 8; i++) { ts += sh[0][i]; tss += sh[1][i]; tc += sh[2][i]; }
        atomicAdd(&g_psum[b], ts);
        atomicAdd(&g_psumsq[b], tss);
        atomicAdd(&g_pcnt[b], tc);
    }
}

// -------- 3) opes (masked, ragged) + mas stats: one block per instance --------
__global__ void opes_mas_stats_k(const float* __restrict__ opes,
                                 const float* __restrict__ mas,
                                 const int* __restrict__ nums) {
    int b = blockIdx.x;
    int n = nums[b];

    float s[FO], q[FO];
#pragma unroll
    for (int f = 0; f < FO; f++) { s[f] = 0.f; q[f] = 0.f; }

    const float4* op = (const float4*)(opes + (size_t)b * S * FO);
    for (int r = threadIdx.x; r < n; r += 256) {
        float4 a  = op[r * 2];
        float4 b4 = op[r * 2 + 1];
        float x[FO] = {a.x, a.y, a.z, a.w, b4.x, b4.y, b4.z, b4.w};
#pragma unroll
        for (int f = 0; f < FO; f++) { s[f] += x[f]; q[f] += x[f] * x[f]; }
    }

    __shared__ float sh[16][8];
    int lane = threadIdx.x & 31, w = threadIdx.x >> 5;
#pragma unroll
    for (int f = 0; f < FO; f++) {
        float rs = warp_sum(s[f]);
        float rq = warp_sum(q[f]);
        if (lane == 0) { sh[f][w] = rs; sh[f + 8][w] = rq; }
    }
    __syncthreads();

    if (threadIdx.x < FO) {
        int f = threadIdx.x;
        float ts = 0.f, tq = 0.f;
#pragma unroll
        for (int i = 0; i < 8; i++) { ts += sh[f][i]; tq += sh[f + 8][i]; }
        float fn  = (float)n;
        float m   = ts / fn;
        float var = (tq - ts * ts / fn) / (fn - 1.f);
        g_omean[b * FO + f] = m;
        g_orstd[b * FO + f] = 1.f / (sqrtf(var) + EPSF);
    }

    // mas: tiny (64 x 6 per instance). Spare warp handles it serially.
    if (threadIdx.x >= 32 && threadIdx.x < 32 + FM) {
        int f = threadIdx.x - 32;
        const float* mp = mas + (size_t)b * NM * FM + f;
        float ts = 0.f, tq = 0.f;
#pragma unroll
        for (int m = 0; m < NM; m++) { float x = mp[m * FM]; ts += x; tq += x * x; }
        float fm  = (float)NM;
        float mean = ts / fm;
        float var  = (tq - ts * ts / fm) / (fm - 1.f);
        g_mmean[b * FM + f] = mean;
        g_mrstd[b * FM + f] = 1.f / (sqrtf(var) + EPSF);
    }
}

// -------- 4) finalize proc stats --------
__global__ void proc_finalize_k() {
    int b = threadIdx.x;
    if (b < NB) {
        float s = g_psum[b], ss = g_psumsq[b], c = g_pcnt[b];
        float m   = s / c;
        float var = (ss - s * s / c) / (c - 1.f);
        g_pmean[b] = m;
        g_prstd[b] = 1.f / (sqrtf(var) + EPSF);
    }
}

// -------- 5) normalize opes (float4) --------
__global__ void norm_opes_k(const float4* __restrict__ in, float4* __restrict__ out) {
    const int N4 = NB * S * FO / 4;  // 2097152
    for (int i = blockIdx.x * blockDim.x + threadIdx.x; i < N4; i += gridDim.x * blockDim.x) {
        int b = i >> 13;            // 8192 float4 per instance
        int c = (i & 1) * 4;        // feature base within the 8-wide row
        float4 v = in[i];
        const float* mm = &g_omean[b * FO + c];
        const float* rr = &g_orstd[b * FO + c];
        float4 o;
        o.x = (v.x - mm[0]) * rr[0];
        o.y = (v.y - mm[1]) * rr[1];
        o.z = (v.z - mm[2]) * rr[2];
        o.w = (v.w - mm[3]) * rr[3];
        out[i] = o;
    }
}

// -------- 6) normalize mas (scalar; 98K elements, negligible) --------
__global__ void norm_mas_k(const float* __restrict__ in, float* __restrict__ out) {
    const int N = NB * NM * FM;
    int i = blockIdx.x * blockDim.x + threadIdx.x;
    if (i < N) {
        int b = i / (NM * FM);
        int f = i % FM;
        out[i] = (in[i] - g_mmean[b * FM + f]) * g_mrstd[b * FM + f];
    }
}

// -------- 7) normalize proc (float4, reversed traversal for L2 tail reuse) --------
__global__ void norm_proc_k(const float4* __restrict__ in, float4* __restrict__ out) {
    const int N4 = NB * S * NM / 4;  // 16777216
    for (int i0 = blockIdx.x * blockDim.x + threadIdx.x; i0 < N4; i0 += gridDim.x * blockDim.x) {
        int i = N4 - 1 - i0;         // tail instances were reduced last -> still L2-hot
        int b = i >> 16;             // 65536 float4 per instance
        float m = g_pmean[b];
        float r = g_prstd[b];
        float4 v = in[i];
        float4 o;
        o.x = (v.x != 0.f) ? (v.x - m) * r : 0.f;
        o.y = (v.y != 0.f) ? (v.y - m) * r : 0.f;
        o.z = (v.z != 0.f) ? (v.z - m) * r : 0.f;
        o.w = (v.w != 0.f) ? (v.w - m) * r : 0.f;
        out[i] = o;
    }
}

extern "C" void kernel_launch(void* const* d_in, const int* in_sizes, int n_in,
                              void* d_out, int out_size) {
    const float* raw_opes = (const float*)d_in[0];
    const float* raw_mas  = (const float*)d_in[1];
    const float* proc     = (const float*)d_in[2];
    const int*   nums     = (const int*)d_in[3];

    float* out_opes = (float*)d_out;
    float* out_mas  = out_opes + (size_t)NB * S * FO;          // +8388608
    float* out_proc = out_mas  + (size_t)NB * NM * FM;         // +98304

    zero_k<<<1, 256>>>();
    proc_reduce_k<<<NB * PBLK, 256>>>((const float4*)proc);
    opes_mas_stats_k<<<NB, 256>>>(raw_opes, raw_mas, nums);
    proc_finalize_k<<<1, 256>>>();
    norm_opes_k<<<2048, 256>>>((const float4*)raw_opes, (float4*)out_opes);
    norm_mas_k<<<(NB * NM * FM + 255) / 256, 256>>>(raw_mas, out_mas);
    norm_proc_k<<<8192, 256>>>((const float4*)proc, (float4*)out_proc);
}